// round 1
// baseline (speedup 1.0000x reference)
#include <cuda_runtime.h>

// ---------------------------------------------------------------------------
// APPNP: h0 = relu(feats@W1+b1)@W2+b2 ; K=10 rounds of
//        h = 0.9 * (scatter_add(gather(h*norm_out, src), dst) * norm_in) + 0.1*h0
// ---------------------------------------------------------------------------

#define N_NODES 100000
#define OUT_DIM 48
#define HID_DIM 256
#define IN_DIM  512

// Scratch (device globals — allocation APIs are forbidden)
__device__ __align__(16) float g_hidden[(size_t)N_NODES * HID_DIM];   // 102.4 MB
__device__ __align__(16) float g_h0[(size_t)N_NODES * OUT_DIM];
__device__ __align__(16) float g_h[(size_t)N_NODES * OUT_DIM];
__device__ __align__(16) float g_hs[(size_t)N_NODES * OUT_DIM];       // h * norm_out
__device__ __align__(16) float g_agg[(size_t)N_NODES * OUT_DIM];
__device__ float g_deg_out[N_NODES];
__device__ float g_deg_in[N_NODES];
__device__ float g_norm_out[N_NODES];
__device__ float g_norm_in[N_NODES];

// ---------------------------------------------------------------------------
// Degree / norm kernels
// ---------------------------------------------------------------------------
__global__ void zero_deg_kernel(int n) {
    int i = blockIdx.x * blockDim.x + threadIdx.x;
    if (i < n) { g_deg_out[i] = 0.f; g_deg_in[i] = 0.f; }
}

__global__ void deg_kernel(const int* __restrict__ src, const int* __restrict__ dst, int e) {
    int i = blockIdx.x * blockDim.x + threadIdx.x;
    if (i < e) {
        atomicAdd(&g_deg_out[src[i]], 1.f);
        atomicAdd(&g_deg_in[dst[i]], 1.f);
    }
}

__global__ void norm_kernel(int n) {
    int i = blockIdx.x * blockDim.x + threadIdx.x;
    if (i < n) {
        g_norm_out[i] = rsqrtf(fmaxf(g_deg_out[i], 1.f));
        g_norm_in[i]  = rsqrtf(fmaxf(g_deg_in[i], 1.f));
    }
}

// ---------------------------------------------------------------------------
// GEMM1: hidden = relu(feats[M,512] @ W1[512,256] + b1)   (fp32 SIMT tiled)
// BM=128, BN=64, BK=16, 256 threads, 8x4 micro-tile per thread
// ---------------------------------------------------------------------------
__global__ __launch_bounds__(256) void gemm1_kernel(
    const float* __restrict__ A, const float* __restrict__ W,
    const float* __restrict__ bias, int M)
{
    __shared__ float As[16][128];
    __shared__ float Bs[16][64];

    const int tid = threadIdx.x;
    const int tx = tid & 15, ty = tid >> 4;
    const int m0 = blockIdx.y * 128;
    const int n0 = blockIdx.x * 64;

    float acc[8][4];
#pragma unroll
    for (int i = 0; i < 8; i++)
#pragma unroll
        for (int j = 0; j < 4; j++) acc[i][j] = 0.f;

    for (int k0 = 0; k0 < IN_DIM; k0 += 16) {
        // A tile: 128x16 = 512 float4
#pragma unroll
        for (int s = 0; s < 2; s++) {
            int f4 = tid + s * 256;
            int m = f4 >> 2;
            int kk4 = (f4 & 3) * 4;
            float4 v = make_float4(0.f, 0.f, 0.f, 0.f);
            if (m0 + m < M)
                v = *(const float4*)&A[(size_t)(m0 + m) * IN_DIM + k0 + kk4];
            As[kk4 + 0][m] = v.x; As[kk4 + 1][m] = v.y;
            As[kk4 + 2][m] = v.z; As[kk4 + 3][m] = v.w;
        }
        // B tile: 16x64 = 256 float4 (K=512, N=256 exact, no guard)
        {
            int kk = tid >> 4;
            int n4 = (tid & 15) * 4;
            float4 v = *(const float4*)&W[(k0 + kk) * 256 + n0 + n4];
            *(float4*)&Bs[kk][n4] = v;
        }
        __syncthreads();

#pragma unroll
        for (int kk = 0; kk < 16; kk++) {
            float a[8], b[4];
#pragma unroll
            for (int i = 0; i < 8; i++) a[i] = As[kk][ty + 16 * i];
#pragma unroll
            for (int j = 0; j < 4; j++) b[j] = Bs[kk][tx + 16 * j];
#pragma unroll
            for (int i = 0; i < 8; i++)
#pragma unroll
                for (int j = 0; j < 4; j++) acc[i][j] += a[i] * b[j];
        }
        __syncthreads();
    }

#pragma unroll
    for (int j = 0; j < 4; j++) {
        float bb = bias[n0 + tx + 16 * j];
#pragma unroll
        for (int i = 0; i < 8; i++) {
            int m = m0 + ty + 16 * i;
            if (m < M)
                g_hidden[(size_t)m * HID_DIM + n0 + tx + 16 * j] = fmaxf(acc[i][j] + bb, 0.f);
        }
    }
}

// ---------------------------------------------------------------------------
// GEMM2: h0 = hidden[M,256] @ W2[256,48] + b2
// 256 threads/block, 128 rows/block: thread = (row = tid>>1, half = tid&1), 24 cols
// ---------------------------------------------------------------------------
__global__ __launch_bounds__(256) void gemm2_kernel(
    const float* __restrict__ W2, const float* __restrict__ b2, int M)
{
    __shared__ float Ws[64][48];

    const int tid = threadIdx.x;
    const int row = blockIdx.x * 128 + (tid >> 1);
    const int half = tid & 1;
    const bool ok = (row < M);

    float acc[24];
#pragma unroll
    for (int j = 0; j < 24; j++) acc[j] = 0.f;

    const float4* hid4 = (const float4*)g_hidden;

    for (int kc = 0; kc < 4; kc++) {
        __syncthreads();
        for (int i = tid; i < 64 * 48; i += 256) {
            int kk = i / 48, c = i - kk * 48;
            Ws[kk][c] = W2[(kc * 64 + kk) * 48 + c];
        }
        __syncthreads();
        if (ok) {
#pragma unroll
            for (int k4 = 0; k4 < 16; k4++) {
                float4 a = hid4[(size_t)row * 64 + kc * 16 + k4];
                float av[4] = {a.x, a.y, a.z, a.w};
#pragma unroll
                for (int q = 0; q < 4; q++) {
#pragma unroll
                    for (int j = 0; j < 24; j++)
                        acc[j] += av[q] * Ws[k4 * 4 + q][half * 24 + j];
                }
            }
        }
    }
    if (ok) {
#pragma unroll
        for (int j = 0; j < 24; j++)
            g_h0[(size_t)row * 48 + half * 24 + j] = acc[j] + b2[half * 24 + j];
    }
}

// ---------------------------------------------------------------------------
// Propagation
// ---------------------------------------------------------------------------
// prep: hs = h * norm_out ; agg = 0      (vectorized, n4 = N*12 float4's)
__global__ void prep_kernel(int use_h0, int n4) {
    int i = blockIdx.x * blockDim.x + threadIdx.x;
    if (i >= n4) return;
    int row = i / 12;
    const float4* in4 = (const float4*)(use_h0 ? g_h0 : g_h);
    float no = g_norm_out[row];
    float4 v = in4[i];
    ((float4*)g_hs)[i]  = make_float4(v.x * no, v.y * no, v.z * no, v.w * no);
    ((float4*)g_agg)[i] = make_float4(0.f, 0.f, 0.f, 0.f);
}

// edge: agg[dst] += hs[src]  (12 float4 chunks per edge, vector red)
__global__ __launch_bounds__(256) void edge_kernel(
    const int* __restrict__ src, const int* __restrict__ dst, long nwork)
{
    long t = (long)blockIdx.x * blockDim.x + threadIdx.x;
    if (t >= nwork) return;
    int e = (int)(t / 12);
    int c = (int)(t - (long)e * 12);
    int s = __ldg(&src[e]);
    int d = __ldg(&dst[e]);
    float4 v = ((const float4*)g_hs)[(size_t)s * 12 + c];
    float* p = &g_agg[(size_t)d * 48 + c * 4];
    asm volatile("red.global.add.v4.f32 [%0], {%1,%2,%3,%4};"
                 :: "l"(p), "f"(v.x), "f"(v.y), "f"(v.z), "f"(v.w) : "memory");
}

// combine: out = 0.9 * agg * norm_in + 0.1 * h0
__global__ void combine_kernel(float* __restrict__ dout, int last, int n4) {
    int i = blockIdx.x * blockDim.x + threadIdx.x;
    if (i >= n4) return;
    int row = i / 12;
    float ni = g_norm_in[row];
    float4 a = ((const float4*)g_agg)[i];
    float4 z = ((const float4*)g_h0)[i];
    float4 r = make_float4(0.9f * a.x * ni + 0.1f * z.x,
                           0.9f * a.y * ni + 0.1f * z.y,
                           0.9f * a.z * ni + 0.1f * z.z,
                           0.9f * a.w * ni + 0.1f * z.w);
    float4* out4 = last ? (float4*)dout : (float4*)g_h;
    out4[i] = r;
}

// ---------------------------------------------------------------------------
extern "C" void kernel_launch(void* const* d_in, const int* in_sizes, int n_in,
                              void* d_out, int out_size)
{
    const float* feats = (const float*)d_in[0];
    const int*   src   = (const int*)d_in[1];
    const int*   dst   = (const int*)d_in[2];
    const float* W1    = (const float*)d_in[3];
    const float* b1    = (const float*)d_in[4];
    const float* W2    = (const float*)d_in[5];
    const float* b2    = (const float*)d_in[6];

    const int N = in_sizes[0] / IN_DIM;
    const int E = in_sizes[1];

    // degrees + norms
    zero_deg_kernel<<<(N + 255) / 256, 256>>>(N);
    deg_kernel<<<(E + 255) / 256, 256>>>(src, dst, E);
    norm_kernel<<<(N + 255) / 256, 256>>>(N);

    // MLP
    dim3 g1(HID_DIM / 64, (N + 127) / 128);
    gemm1_kernel<<<g1, 256>>>(feats, W1, b1, N);
    gemm2_kernel<<<(N + 127) / 128, 256>>>(W2, b2, N);

    // propagation
    const int  n4   = N * 12;               // float4 elements of [N,48]
    const long nwork = (long)E * 12;
    const int  nodeBlocks = (n4 + 255) / 256;
    const int  edgeBlocks = (int)((nwork + 255) / 256);

    for (int k = 0; k < 10; k++) {
        prep_kernel<<<nodeBlocks, 256>>>(k == 0 ? 1 : 0, n4);
        edge_kernel<<<edgeBlocks, 256>>>(src, dst, nwork);
        combine_kernel<<<nodeBlocks, 256>>>((float*)d_out, k == 9 ? 1 : 0, n4);
    }
    (void)n_in; (void)out_size;
}

// round 4
// speedup vs baseline: 1.3470x; 1.3470x over previous
#include <cuda_runtime.h>
#include <cstdint>

// ---------------------------------------------------------------------------
// APPNP: h0 = relu(feats@W1+b1)@W2+b2 ; K=10 rounds of
//        h = 0.9 * (scatter_add(gather(h*norm_out, src), dst) * norm_in) + 0.1*h0
// GEMM1 on tf32 mma.sync (sm_80+ path; tcgen05 unavailable: harness targets
// bare sm_100, no 'a' feature set).
// ---------------------------------------------------------------------------

#define N_NODES 100000
#define OUT_DIM 48
#define HID_DIM 256
#define IN_DIM  512

// Scratch (device globals — allocation APIs are forbidden)
__device__ __align__(16) float g_hidden[(size_t)N_NODES * HID_DIM];
__device__ __align__(16) float g_h0[(size_t)N_NODES * OUT_DIM];
__device__ __align__(16) float g_h[(size_t)N_NODES * OUT_DIM];
__device__ __align__(16) float g_hs[(size_t)N_NODES * OUT_DIM];
__device__ __align__(16) float g_agg[(size_t)N_NODES * OUT_DIM];
__device__ float g_deg_out[N_NODES];
__device__ float g_deg_in[N_NODES];
__device__ float g_norm_out[N_NODES];
__device__ float g_norm_in[N_NODES];

// ---------------------------------------------------------------------------
// Degree / norm kernels
// ---------------------------------------------------------------------------
__global__ void zero_deg_kernel(int n) {
    int i = blockIdx.x * blockDim.x + threadIdx.x;
    if (i < n) { g_deg_out[i] = 0.f; g_deg_in[i] = 0.f; }
}
__global__ void deg_kernel(const int* __restrict__ src, const int* __restrict__ dst, int e) {
    int i = blockIdx.x * blockDim.x + threadIdx.x;
    if (i < e) {
        atomicAdd(&g_deg_out[src[i]], 1.f);
        atomicAdd(&g_deg_in[dst[i]], 1.f);
    }
}
__global__ void norm_kernel(int n) {
    int i = blockIdx.x * blockDim.x + threadIdx.x;
    if (i < n) {
        g_norm_out[i] = rsqrtf(fmaxf(g_deg_out[i], 1.f));
        g_norm_in[i]  = rsqrtf(fmaxf(g_deg_in[i], 1.f));
    }
}

// ---------------------------------------------------------------------------
// tf32 helpers
// ---------------------------------------------------------------------------
__device__ __forceinline__ uint32_t f2tf32(float x) {
    uint32_t u;
    asm("cvt.rna.tf32.f32 %0, %1;" : "=r"(u) : "f"(x));
    return u;
}
__device__ __forceinline__ void mma_tf32(float c[4],
                                         uint32_t a0, uint32_t a1, uint32_t a2, uint32_t a3,
                                         uint32_t b0, uint32_t b1)
{
    asm volatile(
        "mma.sync.aligned.m16n8k8.row.col.f32.tf32.tf32.f32 "
        "{%0,%1,%2,%3}, {%4,%5,%6,%7}, {%8,%9}, {%0,%1,%2,%3};"
        : "+f"(c[0]), "+f"(c[1]), "+f"(c[2]), "+f"(c[3])
        : "r"(a0), "r"(a1), "r"(a2), "r"(a3), "r"(b0), "r"(b1));
}

// ---------------------------------------------------------------------------
// GEMM1 (tf32 mma.sync): hidden = relu(feats[M,512] @ W1[512,256] + b1)
// CTA tile 128x64, 256 threads = 8 warps (4 warpM x 2 warpN), warp tile 32x32.
// K chunks of 32 (4 k-steps of 8 per chunk), 16 chunks total.
// SMEM: As[128][36] (row-major, tf32), Bs[64][36] (n-major = W1^T tile, tf32).
// ---------------------------------------------------------------------------
__global__ __launch_bounds__(256, 2) void gemm1_mma_kernel(
    const float* __restrict__ A, const float* __restrict__ W1,
    const float* __restrict__ bias, int M)
{
    __shared__ uint32_t As[128][36];   // 18432 B
    __shared__ uint32_t Bs[64][36];    //  9216 B

    const int tid  = threadIdx.x;
    const int wid  = tid >> 5;
    const int lane = tid & 31;
    const int warpM = wid & 3;         // 0..3  -> rows
    const int warpN = wid >> 2;        // 0..1  -> cols
    const int m0 = blockIdx.y * 128;
    const int n0 = blockIdx.x * 64;

    const int grp = lane >> 2;         // 0..7
    const int qid = lane & 3;          // 0..3

    float acc[2][4][4];
#pragma unroll
    for (int mt = 0; mt < 2; mt++)
#pragma unroll
        for (int nt = 0; nt < 4; nt++)
#pragma unroll
            for (int q = 0; q < 4; q++) acc[mt][nt][q] = 0.f;

    for (int kc = 0; kc < IN_DIM / 32; kc++) {
        const int k0 = kc * 32;

        // --- A tile: 128 rows x 32 cols = 1024 float4, 4 per thread ---
#pragma unroll
        for (int it = 0; it < 4; it++) {
            int f = tid + it * 256;
            int m = f >> 3, k4 = (f & 7) * 4;
            float4 v = make_float4(0.f, 0.f, 0.f, 0.f);
            if (m0 + m < M)
                v = *(const float4*)&A[(size_t)(m0 + m) * IN_DIM + k0 + k4];
            As[m][k4 + 0] = f2tf32(v.x);
            As[m][k4 + 1] = f2tf32(v.y);
            As[m][k4 + 2] = f2tf32(v.z);
            As[m][k4 + 3] = f2tf32(v.w);
        }
        // --- B tile: W1[k0..k0+31][n0..n0+63] -> Bs[n][k] (transpose in smem) ---
#pragma unroll
        for (int it = 0; it < 2; it++) {
            int f = tid + it * 256;                 // 0..511 float4 ids
            int kk = f >> 4, nn4 = (f & 15) * 4;
            float4 v = *(const float4*)&W1[(size_t)(k0 + kk) * HID_DIM + n0 + nn4];
            Bs[nn4 + 0][kk] = f2tf32(v.x);
            Bs[nn4 + 1][kk] = f2tf32(v.y);
            Bs[nn4 + 2][kk] = f2tf32(v.z);
            Bs[nn4 + 3][kk] = f2tf32(v.w);
        }
        __syncthreads();

#pragma unroll
        for (int ks = 0; ks < 4; ks++) {
            const int k = ks * 8;
            // B fragments for 4 n-tiles
            uint32_t bf[4][2];
#pragma unroll
            for (int nt = 0; nt < 4; nt++) {
                int cn = warpN * 32 + nt * 8 + grp;
                bf[nt][0] = Bs[cn][k + qid];
                bf[nt][1] = Bs[cn][k + 4 + qid];
            }
            // A fragments + mma for 2 m-tiles
#pragma unroll
            for (int mt = 0; mt < 2; mt++) {
                int rm = warpM * 32 + mt * 16 + grp;
                uint32_t a0 = As[rm][k + qid];
                uint32_t a1 = As[rm + 8][k + qid];
                uint32_t a2 = As[rm][k + 4 + qid];
                uint32_t a3 = As[rm + 8][k + 4 + qid];
#pragma unroll
                for (int nt = 0; nt < 4; nt++)
                    mma_tf32(acc[mt][nt], a0, a1, a2, a3, bf[nt][0], bf[nt][1]);
            }
        }
        __syncthreads();
    }

    // Epilogue: bias + relu, write float2 pairs
#pragma unroll
    for (int nt = 0; nt < 4; nt++) {
        int col = n0 + warpN * 32 + nt * 8 + 2 * qid;
        float bb0 = __ldg(&bias[col]);
        float bb1 = __ldg(&bias[col + 1]);
#pragma unroll
        for (int mt = 0; mt < 2; mt++) {
            int r0 = m0 + warpM * 32 + mt * 16 + grp;
            if (r0 < M) {
                float2 v = make_float2(fmaxf(acc[mt][nt][0] + bb0, 0.f),
                                       fmaxf(acc[mt][nt][1] + bb1, 0.f));
                *(float2*)&g_hidden[(size_t)r0 * HID_DIM + col] = v;
            }
            if (r0 + 8 < M) {
                float2 v = make_float2(fmaxf(acc[mt][nt][2] + bb0, 0.f),
                                       fmaxf(acc[mt][nt][3] + bb1, 0.f));
                *(float2*)&g_hidden[(size_t)(r0 + 8) * HID_DIM + col] = v;
            }
        }
    }
}

// ---------------------------------------------------------------------------
// GEMM2: h0 = hidden[M,256] @ W2[256,48] + b2  (SIMT)
// ---------------------------------------------------------------------------
__global__ __launch_bounds__(256) void gemm2_kernel(
    const float* __restrict__ W2, const float* __restrict__ b2, int M)
{
    __shared__ float Ws[64][48];
    const int tid = threadIdx.x;
    const int row = blockIdx.x * 128 + (tid >> 1);
    const int half = tid & 1;
    const bool ok = (row < M);

    float acc[24];
#pragma unroll
    for (int j = 0; j < 24; j++) acc[j] = 0.f;

    const float4* hid4 = (const float4*)g_hidden;
    for (int kc = 0; kc < 4; kc++) {
        __syncthreads();
        for (int i = tid; i < 64 * 48; i += 256) {
            int kk = i / 48, c = i - kk * 48;
            Ws[kk][c] = W2[(kc * 64 + kk) * 48 + c];
        }
        __syncthreads();
        if (ok) {
#pragma unroll
            for (int k4 = 0; k4 < 16; k4++) {
                float4 a = hid4[(size_t)row * 64 + kc * 16 + k4];
                float av[4] = {a.x, a.y, a.z, a.w};
#pragma unroll
                for (int q = 0; q < 4; q++)
#pragma unroll
                    for (int j = 0; j < 24; j++)
                        acc[j] += av[q] * Ws[k4 * 4 + q][half * 24 + j];
            }
        }
    }
    if (ok) {
#pragma unroll
        for (int j = 0; j < 24; j++)
            g_h0[(size_t)row * 48 + half * 24 + j] = acc[j] + b2[half * 24 + j];
    }
}

// ---------------------------------------------------------------------------
// Propagation
// ---------------------------------------------------------------------------
__global__ void prep_kernel(int use_h0, int n4) {
    int i = blockIdx.x * blockDim.x + threadIdx.x;
    if (i >= n4) return;
    int row = i / 12;
    const float4* in4 = (const float4*)(use_h0 ? g_h0 : g_h);
    float no = g_norm_out[row];
    float4 v = in4[i];
    ((float4*)g_hs)[i]  = make_float4(v.x * no, v.y * no, v.z * no, v.w * no);
    ((float4*)g_agg)[i] = make_float4(0.f, 0.f, 0.f, 0.f);
}

__global__ __launch_bounds__(256) void edge_kernel(
    const int* __restrict__ src, const int* __restrict__ dst, long nwork)
{
    long t = (long)blockIdx.x * blockDim.x + threadIdx.x;
    if (t >= nwork) return;
    int e = (int)(t / 12);
    int c = (int)(t - (long)e * 12);
    int s = __ldg(&src[e]);
    int d = __ldg(&dst[e]);
    float4 v = ((const float4*)g_hs)[(size_t)s * 12 + c];
    float* p = &g_agg[(size_t)d * 48 + c * 4];
    asm volatile("red.global.add.v4.f32 [%0], {%1,%2,%3,%4};"
                 :: "l"(p), "f"(v.x), "f"(v.y), "f"(v.z), "f"(v.w) : "memory");
}

__global__ void combine_kernel(float* __restrict__ dout, int last, int n4) {
    int i = blockIdx.x * blockDim.x + threadIdx.x;
    if (i >= n4) return;
    int row = i / 12;
    float ni = g_norm_in[row];
    float4 a = ((const float4*)g_agg)[i];
    float4 z = ((const float4*)g_h0)[i];
    float4 r = make_float4(0.9f * a.x * ni + 0.1f * z.x,
                           0.9f * a.y * ni + 0.1f * z.y,
                           0.9f * a.z * ni + 0.1f * z.z,
                           0.9f * a.w * ni + 0.1f * z.w);
    float4* out4 = last ? (float4*)dout : (float4*)g_h;
    out4[i] = r;
}

// ---------------------------------------------------------------------------
extern "C" void kernel_launch(void* const* d_in, const int* in_sizes, int n_in,
                              void* d_out, int out_size)
{
    const float* feats = (const float*)d_in[0];
    const int*   src   = (const int*)d_in[1];
    const int*   dst   = (const int*)d_in[2];
    const float* W1    = (const float*)d_in[3];
    const float* b1    = (const float*)d_in[4];
    const float* W2    = (const float*)d_in[5];
    const float* b2    = (const float*)d_in[6];

    const int N = in_sizes[0] / IN_DIM;
    const int E = in_sizes[1];

    // degrees + norms
    zero_deg_kernel<<<(N + 255) / 256, 256>>>(N);
    deg_kernel<<<(E + 255) / 256, 256>>>(src, dst, E);
    norm_kernel<<<(N + 255) / 256, 256>>>(N);

    // MLP
    dim3 g1(HID_DIM / 64, (N + 127) / 128);
    gemm1_mma_kernel<<<g1, 256>>>(feats, W1, b1, N);
    gemm2_kernel<<<(N + 127) / 128, 256>>>(W2, b2, N);

    // propagation
    const int  n4    = N * 12;
    const long nwork = (long)E * 12;
    const int  nodeBlocks = (n4 + 255) / 256;
    const int  edgeBlocks = (int)((nwork + 255) / 256);

    for (int k = 0; k < 10; k++) {
        prep_kernel<<<nodeBlocks, 256>>>(k == 0 ? 1 : 0, n4);
        edge_kernel<<<edgeBlocks, 256>>>(src, dst, nwork);
        combine_kernel<<<nodeBlocks, 256>>>((float*)d_out, k == 9 ? 1 : 0, n4);
    }
    (void)n_in; (void)out_size;
}

// round 5
// speedup vs baseline: 2.2267x; 1.6530x over previous
#include <cuda_runtime.h>
#include <cstdint>

// ---------------------------------------------------------------------------
// APPNP. GEMM1 on tf32 mma.sync. Propagation via per-launch CSR(dst) build +
// one fused gather-reduce kernel per iteration (no atomics in the hot loop).
// ---------------------------------------------------------------------------

#define N_NODES 100000
#define E_EDGES 1600000
#define OUT_DIM 48
#define HID_DIM 256
#define IN_DIM  512

// Scratch (device globals — allocation APIs are forbidden)
__device__ __align__(16) float g_hidden[(size_t)N_NODES * HID_DIM];
__device__ __align__(16) float g_h0[(size_t)N_NODES * OUT_DIM];
__device__ __align__(16) float g_hsA[(size_t)N_NODES * OUT_DIM];
__device__ __align__(16) float g_hsB[(size_t)N_NODES * OUT_DIM];
__device__ int   g_ideg_out[N_NODES];
__device__ int   g_ideg_in[N_NODES];
__device__ float g_norm_out[N_NODES];
__device__ float g_norm_in[N_NODES];
__device__ int   g_off[N_NODES + 1];
__device__ int   g_cursor[N_NODES];
__device__ int   g_blocksums[512];
__device__ int   g_csr_src[E_EDGES];

// ---------------------------------------------------------------------------
// Degrees / norms (int atomics)
// ---------------------------------------------------------------------------
__global__ void zero_deg_kernel(int n) {
    int i = blockIdx.x * blockDim.x + threadIdx.x;
    if (i < n) { g_ideg_out[i] = 0; g_ideg_in[i] = 0; }
}
__global__ void deg_kernel(const int* __restrict__ src, const int* __restrict__ dst, int e) {
    int i = blockIdx.x * blockDim.x + threadIdx.x;
    if (i < e) {
        atomicAdd(&g_ideg_out[src[i]], 1);
        atomicAdd(&g_ideg_in[dst[i]], 1);
    }
}
__global__ void norm_kernel(int n) {
    int i = blockIdx.x * blockDim.x + threadIdx.x;
    if (i < n) {
        g_norm_out[i] = rsqrtf((float)max(g_ideg_out[i], 1));
        g_norm_in[i]  = rsqrtf((float)max(g_ideg_in[i], 1));
    }
}

// ---------------------------------------------------------------------------
// Prefix sum over g_ideg_in -> g_off (exclusive; off[0]=0, off[i+1]=incl[i])
// scanA: per-block (256) inclusive scan; scanB: scan of block sums;
// scanC: add block offsets; cursor_init: cursor = off.
// ---------------------------------------------------------------------------
__global__ void scanA_kernel(int n) {
    __shared__ int sh[256];
    int i = blockIdx.x * 256 + threadIdx.x;
    sh[threadIdx.x] = (i < n) ? g_ideg_in[i] : 0;
    __syncthreads();
#pragma unroll
    for (int d = 1; d < 256; d <<= 1) {
        int t = (threadIdx.x >= d) ? sh[threadIdx.x - d] : 0;
        __syncthreads();
        sh[threadIdx.x] += t;
        __syncthreads();
    }
    if (i < n) g_off[i + 1] = sh[threadIdx.x];
    if (threadIdx.x == 255) g_blocksums[blockIdx.x] = sh[255];
}
__global__ void scanB_kernel(int nb) {
    __shared__ int sh[512];
    int t = threadIdx.x;
    sh[t] = (t < nb) ? g_blocksums[t] : 0;
    __syncthreads();
#pragma unroll
    for (int d = 1; d < 512; d <<= 1) {
        int x = (t >= d) ? sh[t - d] : 0;
        __syncthreads();
        sh[t] += x;
        __syncthreads();
    }
    if (t < nb) g_blocksums[t] = sh[t];     // inclusive block sums
}
__global__ void scanC_kernel(int n) {
    int i = blockIdx.x * 256 + threadIdx.x;
    if (i < n) {
        int add = (blockIdx.x > 0) ? g_blocksums[blockIdx.x - 1] : 0;
        g_off[i + 1] += add;
    }
    if (i == 0) g_off[0] = 0;
}
__global__ void cursor_init_kernel(int n) {
    int i = blockIdx.x * blockDim.x + threadIdx.x;
    if (i < n) g_cursor[i] = g_off[i];
}
__global__ void scatter_kernel(const int* __restrict__ src, const int* __restrict__ dst, int e) {
    int i = blockIdx.x * blockDim.x + threadIdx.x;
    if (i < e) {
        int p = atomicAdd(&g_cursor[dst[i]], 1);
        g_csr_src[p] = src[i];
    }
}

// ---------------------------------------------------------------------------
// tf32 helpers
// ---------------------------------------------------------------------------
__device__ __forceinline__ uint32_t f2tf32(float x) {
    uint32_t u;
    asm("cvt.rna.tf32.f32 %0, %1;" : "=r"(u) : "f"(x));
    return u;
}
__device__ __forceinline__ void mma_tf32(float c[4],
                                         uint32_t a0, uint32_t a1, uint32_t a2, uint32_t a3,
                                         uint32_t b0, uint32_t b1)
{
    asm volatile(
        "mma.sync.aligned.m16n8k8.row.col.f32.tf32.tf32.f32 "
        "{%0,%1,%2,%3}, {%4,%5,%6,%7}, {%8,%9}, {%0,%1,%2,%3};"
        : "+f"(c[0]), "+f"(c[1]), "+f"(c[2]), "+f"(c[3])
        : "r"(a0), "r"(a1), "r"(a2), "r"(a3), "r"(b0), "r"(b1));
}

// ---------------------------------------------------------------------------
// GEMM1 (tf32 mma.sync): hidden = relu(feats[M,512] @ W1[512,256] + b1)
// (unchanged from Round 4 passing version)
// ---------------------------------------------------------------------------
__global__ __launch_bounds__(256, 2) void gemm1_mma_kernel(
    const float* __restrict__ A, const float* __restrict__ W1,
    const float* __restrict__ bias, int M)
{
    __shared__ uint32_t As[128][36];
    __shared__ uint32_t Bs[64][36];

    const int tid  = threadIdx.x;
    const int wid  = tid >> 5;
    const int lane = tid & 31;
    const int warpM = wid & 3;
    const int warpN = wid >> 2;
    const int m0 = blockIdx.y * 128;
    const int n0 = blockIdx.x * 64;

    const int grp = lane >> 2;
    const int qid = lane & 3;

    float acc[2][4][4];
#pragma unroll
    for (int mt = 0; mt < 2; mt++)
#pragma unroll
        for (int nt = 0; nt < 4; nt++)
#pragma unroll
            for (int q = 0; q < 4; q++) acc[mt][nt][q] = 0.f;

    for (int kc = 0; kc < IN_DIM / 32; kc++) {
        const int k0 = kc * 32;
#pragma unroll
        for (int it = 0; it < 4; it++) {
            int f = tid + it * 256;
            int m = f >> 3, k4 = (f & 7) * 4;
            float4 v = make_float4(0.f, 0.f, 0.f, 0.f);
            if (m0 + m < M)
                v = *(const float4*)&A[(size_t)(m0 + m) * IN_DIM + k0 + k4];
            As[m][k4 + 0] = f2tf32(v.x);
            As[m][k4 + 1] = f2tf32(v.y);
            As[m][k4 + 2] = f2tf32(v.z);
            As[m][k4 + 3] = f2tf32(v.w);
        }
#pragma unroll
        for (int it = 0; it < 2; it++) {
            int f = tid + it * 256;
            int kk = f >> 4, nn4 = (f & 15) * 4;
            float4 v = *(const float4*)&W1[(size_t)(k0 + kk) * HID_DIM + n0 + nn4];
            Bs[nn4 + 0][kk] = f2tf32(v.x);
            Bs[nn4 + 1][kk] = f2tf32(v.y);
            Bs[nn4 + 2][kk] = f2tf32(v.z);
            Bs[nn4 + 3][kk] = f2tf32(v.w);
        }
        __syncthreads();

#pragma unroll
        for (int ks = 0; ks < 4; ks++) {
            const int k = ks * 8;
            uint32_t bf[4][2];
#pragma unroll
            for (int nt = 0; nt < 4; nt++) {
                int cn = warpN * 32 + nt * 8 + grp;
                bf[nt][0] = Bs[cn][k + qid];
                bf[nt][1] = Bs[cn][k + 4 + qid];
            }
#pragma unroll
            for (int mt = 0; mt < 2; mt++) {
                int rm = warpM * 32 + mt * 16 + grp;
                uint32_t a0 = As[rm][k + qid];
                uint32_t a1 = As[rm + 8][k + qid];
                uint32_t a2 = As[rm][k + 4 + qid];
                uint32_t a3 = As[rm + 8][k + 4 + qid];
#pragma unroll
                for (int nt = 0; nt < 4; nt++)
                    mma_tf32(acc[mt][nt], a0, a1, a2, a3, bf[nt][0], bf[nt][1]);
            }
        }
        __syncthreads();
    }

#pragma unroll
    for (int nt = 0; nt < 4; nt++) {
        int col = n0 + warpN * 32 + nt * 8 + 2 * qid;
        float bb0 = __ldg(&bias[col]);
        float bb1 = __ldg(&bias[col + 1]);
#pragma unroll
        for (int mt = 0; mt < 2; mt++) {
            int r0 = m0 + warpM * 32 + mt * 16 + grp;
            if (r0 < M) {
                float2 v = make_float2(fmaxf(acc[mt][nt][0] + bb0, 0.f),
                                       fmaxf(acc[mt][nt][1] + bb1, 0.f));
                *(float2*)&g_hidden[(size_t)r0 * HID_DIM + col] = v;
            }
            if (r0 + 8 < M) {
                float2 v = make_float2(fmaxf(acc[mt][nt][2] + bb0, 0.f),
                                       fmaxf(acc[mt][nt][3] + bb1, 0.f));
                *(float2*)&g_hidden[(size_t)(r0 + 8) * HID_DIM + col] = v;
            }
        }
    }
}

// ---------------------------------------------------------------------------
// GEMM2: h0 = hidden[M,256] @ W2[256,48] + b2  (SIMT)
// ---------------------------------------------------------------------------
__global__ __launch_bounds__(256) void gemm2_kernel(
    const float* __restrict__ W2, const float* __restrict__ b2, int M)
{
    __shared__ float Ws[64][48];
    const int tid = threadIdx.x;
    const int row = blockIdx.x * 128 + (tid >> 1);
    const int half = tid & 1;
    const bool ok = (row < M);

    float acc[24];
#pragma unroll
    for (int j = 0; j < 24; j++) acc[j] = 0.f;

    const float4* hid4 = (const float4*)g_hidden;
    for (int kc = 0; kc < 4; kc++) {
        __syncthreads();
        for (int i = tid; i < 64 * 48; i += 256) {
            int kk = i / 48, c = i - kk * 48;
            Ws[kk][c] = W2[(kc * 64 + kk) * 48 + c];
        }
        __syncthreads();
        if (ok) {
#pragma unroll
            for (int k4 = 0; k4 < 16; k4++) {
                float4 a = hid4[(size_t)row * 64 + kc * 16 + k4];
                float av[4] = {a.x, a.y, a.z, a.w};
#pragma unroll
                for (int q = 0; q < 4; q++)
#pragma unroll
                    for (int j = 0; j < 24; j++)
                        acc[j] += av[q] * Ws[k4 * 4 + q][half * 24 + j];
            }
        }
    }
    if (ok) {
#pragma unroll
        for (int j = 0; j < 24; j++)
            g_h0[(size_t)row * 48 + half * 24 + j] = acc[j] + b2[half * 24 + j];
    }
}

// ---------------------------------------------------------------------------
// Propagation (CSR, fused, atomic-free)
// ---------------------------------------------------------------------------
// hs0 = h0 * norm_out  (into g_hsA)
__global__ void hs0_kernel(int n4) {
    int i = blockIdx.x * blockDim.x + threadIdx.x;
    if (i >= n4) return;
    int row = i / 12;
    float no = g_norm_out[row];
    float4 v = ((const float4*)g_h0)[i];
    ((float4*)g_hsA)[i] = make_float4(v.x * no, v.y * no, v.z * no, v.w * no);
}

// One iteration: for each node g, acc = sum over in-edges of hs_in[src];
// h = 0.9*acc*norm_in + 0.1*h0 ; hs_out = h*norm_out (or d_out on last iter).
// 12 threads per node (one float4 chunk each), blockDim 384 -> 32 nodes/block.
__global__ __launch_bounds__(384) void agg_kernel(
    float* __restrict__ dout, int parity, int last, int n)
{
    int t = blockIdx.x * 384 + threadIdx.x;
    int g = t / 12;
    int c = t - g * 12;
    if (g >= n) return;

    const float4* hin  = (const float4*)(parity ? g_hsB : g_hsA);
    float4*       hout = (float4*)(parity ? g_hsA : g_hsB);

    int i   = g_off[g];
    int end = g_off[g + 1];
    float4 acc = make_float4(0.f, 0.f, 0.f, 0.f);

    for (; i + 3 < end; i += 4) {
        int s0 = __ldg(&g_csr_src[i]);
        int s1 = __ldg(&g_csr_src[i + 1]);
        int s2 = __ldg(&g_csr_src[i + 2]);
        int s3 = __ldg(&g_csr_src[i + 3]);
        float4 v0 = hin[(size_t)s0 * 12 + c];
        float4 v1 = hin[(size_t)s1 * 12 + c];
        float4 v2 = hin[(size_t)s2 * 12 + c];
        float4 v3 = hin[(size_t)s3 * 12 + c];
        acc.x += v0.x + v1.x + v2.x + v3.x;
        acc.y += v0.y + v1.y + v2.y + v3.y;
        acc.z += v0.z + v1.z + v2.z + v3.z;
        acc.w += v0.w + v1.w + v2.w + v3.w;
    }
    for (; i < end; i++) {
        int s = __ldg(&g_csr_src[i]);
        float4 v = hin[(size_t)s * 12 + c];
        acc.x += v.x; acc.y += v.y; acc.z += v.z; acc.w += v.w;
    }

    float ni = g_norm_in[g];
    float4 z = ((const float4*)g_h0)[(size_t)g * 12 + c];
    float4 h = make_float4(0.9f * acc.x * ni + 0.1f * z.x,
                           0.9f * acc.y * ni + 0.1f * z.y,
                           0.9f * acc.z * ni + 0.1f * z.z,
                           0.9f * acc.w * ni + 0.1f * z.w);
    if (last) {
        ((float4*)dout)[(size_t)g * 12 + c] = h;
    } else {
        float no = g_norm_out[g];
        hout[(size_t)g * 12 + c] = make_float4(h.x * no, h.y * no, h.z * no, h.w * no);
    }
}

// ---------------------------------------------------------------------------
extern "C" void kernel_launch(void* const* d_in, const int* in_sizes, int n_in,
                              void* d_out, int out_size)
{
    const float* feats = (const float*)d_in[0];
    const int*   src   = (const int*)d_in[1];
    const int*   dst   = (const int*)d_in[2];
    const float* W1    = (const float*)d_in[3];
    const float* b1    = (const float*)d_in[4];
    const float* W2    = (const float*)d_in[5];
    const float* b2    = (const float*)d_in[6];

    const int N = in_sizes[0] / IN_DIM;
    const int E = in_sizes[1];

    // degrees + norms
    zero_deg_kernel<<<(N + 255) / 256, 256>>>(N);
    deg_kernel<<<(E + 255) / 256, 256>>>(src, dst, E);
    norm_kernel<<<(N + 255) / 256, 256>>>(N);

    // CSR build (by dst)
    const int scanBlocks = (N + 255) / 256;
    scanA_kernel<<<scanBlocks, 256>>>(N);
    scanB_kernel<<<1, 512>>>(scanBlocks);
    scanC_kernel<<<scanBlocks, 256>>>(N);
    cursor_init_kernel<<<(N + 255) / 256, 256>>>(N);
    scatter_kernel<<<(E + 255) / 256, 256>>>(src, dst, E);

    // MLP
    dim3 g1(HID_DIM / 64, (N + 127) / 128);
    gemm1_mma_kernel<<<g1, 256>>>(feats, W1, b1, N);
    gemm2_kernel<<<(N + 127) / 128, 256>>>(W2, b2, N);

    // propagation
    const int n4 = N * 12;
    hs0_kernel<<<(n4 + 255) / 256, 256>>>(n4);
    const int aggBlocks = (N * 12 + 383) / 384;
    for (int k = 0; k < 10; k++) {
        agg_kernel<<<aggBlocks, 384>>>((float*)d_out, k & 1, k == 9 ? 1 : 0, N);
    }
    (void)n_in; (void)out_size;
}

// round 8
// speedup vs baseline: 2.5135x; 1.1288x over previous
#include <cuda_runtime.h>
#include <cstdint>

// ---------------------------------------------------------------------------
// APPNP. GEMM1 on tf32 mma.sync with 3-stage cp.async pipeline (static SMEM,
// <48KB, no cudaFuncSetAttribute). Propagation via CSR(dst) + fused gather.
// ---------------------------------------------------------------------------

#define N_NODES 100000
#define E_EDGES 1600000
#define OUT_DIM 48
#define HID_DIM 256
#define IN_DIM  512

// Scratch (device globals — allocation APIs are forbidden)
__device__ __align__(16) float g_hidden[(size_t)N_NODES * HID_DIM];
__device__ __align__(16) float g_h0[(size_t)N_NODES * OUT_DIM];
__device__ __align__(16) float g_hsA[(size_t)N_NODES * OUT_DIM];
__device__ __align__(16) float g_hsB[(size_t)N_NODES * OUT_DIM];
__device__ int   g_ideg_out[N_NODES];
__device__ int   g_ideg_in[N_NODES];
__device__ float g_norm_out[N_NODES];
__device__ float g_norm_in[N_NODES];
__device__ int   g_off[N_NODES + 1];
__device__ int   g_cursor[N_NODES];
__device__ int   g_blocksums[512];
__device__ int   g_csr_src[E_EDGES];

// ---------------------------------------------------------------------------
// Degrees / norms
// ---------------------------------------------------------------------------
__global__ void zero_deg_kernel(int n) {
    int i = blockIdx.x * blockDim.x + threadIdx.x;
    if (i < n) { g_ideg_out[i] = 0; g_ideg_in[i] = 0; }
}
__global__ void deg_kernel(const int* __restrict__ src, const int* __restrict__ dst, int e) {
    int i = blockIdx.x * blockDim.x + threadIdx.x;
    if (i < e) {
        atomicAdd(&g_ideg_out[src[i]], 1);
        atomicAdd(&g_ideg_in[dst[i]], 1);
    }
}
__global__ void norm_kernel(int n) {
    int i = blockIdx.x * blockDim.x + threadIdx.x;
    if (i < n) {
        g_norm_out[i] = rsqrtf((float)max(g_ideg_out[i], 1));
        g_norm_in[i]  = rsqrtf((float)max(g_ideg_in[i], 1));
    }
}

// ---------------------------------------------------------------------------
// Prefix sum over g_ideg_in -> g_off
// ---------------------------------------------------------------------------
__global__ void scanA_kernel(int n) {
    __shared__ int sh[256];
    int i = blockIdx.x * 256 + threadIdx.x;
    sh[threadIdx.x] = (i < n) ? g_ideg_in[i] : 0;
    __syncthreads();
#pragma unroll
    for (int d = 1; d < 256; d <<= 1) {
        int t = (threadIdx.x >= d) ? sh[threadIdx.x - d] : 0;
        __syncthreads();
        sh[threadIdx.x] += t;
        __syncthreads();
    }
    if (i < n) g_off[i + 1] = sh[threadIdx.x];
    if (threadIdx.x == 255) g_blocksums[blockIdx.x] = sh[255];
}
__global__ void scanB_kernel(int nb) {
    __shared__ int sh[512];
    int t = threadIdx.x;
    sh[t] = (t < nb) ? g_blocksums[t] : 0;
    __syncthreads();
#pragma unroll
    for (int d = 1; d < 512; d <<= 1) {
        int x = (t >= d) ? sh[t - d] : 0;
        __syncthreads();
        sh[t] += x;
        __syncthreads();
    }
    if (t < nb) g_blocksums[t] = sh[t];
}
__global__ void scanC_kernel(int n) {
    int i = blockIdx.x * 256 + threadIdx.x;
    if (i < n) {
        int add = (blockIdx.x > 0) ? g_blocksums[blockIdx.x - 1] : 0;
        g_off[i + 1] += add;
    }
    if (i == 0) g_off[0] = 0;
}
__global__ void cursor_init_kernel(int n) {
    int i = blockIdx.x * blockDim.x + threadIdx.x;
    if (i < n) g_cursor[i] = g_off[i];
}
__global__ void scatter_kernel(const int* __restrict__ src, const int* __restrict__ dst, int e) {
    int i = blockIdx.x * blockDim.x + threadIdx.x;
    if (i < e) {
        int p = atomicAdd(&g_cursor[dst[i]], 1);
        g_csr_src[p] = src[i];
    }
}

// ---------------------------------------------------------------------------
// mma helper (raw fp32 bits -> HW tf32 truncation)
// ---------------------------------------------------------------------------
__device__ __forceinline__ void mma_tf32(float c[4],
                                         uint32_t a0, uint32_t a1, uint32_t a2, uint32_t a3,
                                         uint32_t b0, uint32_t b1)
{
    asm volatile(
        "mma.sync.aligned.m16n8k8.row.col.f32.tf32.tf32.f32 "
        "{%0,%1,%2,%3}, {%4,%5,%6,%7}, {%8,%9}, {%0,%1,%2,%3};"
        : "+f"(c[0]), "+f"(c[1]), "+f"(c[2]), "+f"(c[3])
        : "r"(a0), "r"(a1), "r"(a2), "r"(a3), "r"(b0), "r"(b1));
}

__device__ __forceinline__ uint32_t smem_u32(const void* p) {
    uint32_t a;
    asm("{ .reg .u64 t; cvta.to.shared.u64 t, %1; cvt.u32.u64 %0, t; }" : "=r"(a) : "l"(p));
    return a;
}
__device__ __forceinline__ void cp16(uint32_t dst, const void* src, int szbytes) {
    asm volatile("cp.async.cg.shared.global [%0], [%1], 16, %2;"
                 :: "r"(dst), "l"(src), "r"(szbytes));
}
#define CP_COMMIT() asm volatile("cp.async.commit_group;" ::: "memory")
#define CP_WAIT(n)  asm volatile("cp.async.wait_group %0;" :: "n"(n) : "memory")

// ---------------------------------------------------------------------------
// GEMM1 (tf32 mma.sync, 3-stage cp.async, static SMEM):
//   hidden = relu(feats[M,512] @ W1[512,256] + b1)
// CTA tile 128x64, 8 warps (4 warpM x 2 warpN), warp tile 32x32.
// K chunks of 16 (2 k-steps of 8 each), 32 chunks total, 3 SMEM buffers.
// As stride 20 u32 (bank: 20*grp+qid all-distinct); Bs K-major stride 72
// (bank: 8*qid+grp all-distinct). Total smem = 3*(10240+4608) = 44544 B.
// ---------------------------------------------------------------------------
#define G1_AS_STRIDE 20
#define G1_BS_STRIDE 72
#define G1_NCHUNK    (IN_DIM / 16)   // 32

__global__ __launch_bounds__(256, 2) void gemm1_mma_kernel(
    const float* __restrict__ A, const float* __restrict__ W1,
    const float* __restrict__ bias, int M)
{
    __shared__ uint32_t As[3][128][G1_AS_STRIDE];   // 3 * 10240 B
    __shared__ uint32_t Bs[3][16][G1_BS_STRIDE];    // 3 *  4608 B

    const int tid  = threadIdx.x;
    const int wid  = tid >> 5;
    const int lane = tid & 31;
    const int warpM = wid & 3;
    const int warpN = wid >> 2;
    const int m0 = blockIdx.y * 128;
    const int n0 = blockIdx.x * 64;

    const int grp = lane >> 2;
    const int qid = lane & 3;

    // per-thread load coords (constant across chunks)
    const int a_m0  = tid >> 2;                 // A float4 #0: row
    const int a_k0  = (tid & 3) * 4;            //             col
    const int a_m1  = (tid + 256) >> 2;         // A float4 #1
    const int a_k1  = ((tid + 256) & 3) * 4;
    const int b_kk  = tid >> 4;                 // B float4: k-row
    const int b_nn4 = (tid & 15) * 4;           //           n-col

    float acc[2][4][4];
#pragma unroll
    for (int mt = 0; mt < 2; mt++)
#pragma unroll
        for (int nt = 0; nt < 4; nt++)
#pragma unroll
            for (int q = 0; q < 4; q++) acc[mt][nt][q] = 0.f;

    // issue loads for chunk kc into buffer b
    auto issue = [&](int kc, int b) {
        const int k0 = kc * 16;
        const uint32_t abase = smem_u32(&As[b][0][0]);
        const uint32_t bbase = smem_u32(&Bs[b][0][0]);
        int sz0 = (m0 + a_m0 < M) ? 16 : 0;
        cp16(abase + (uint32_t)(a_m0 * G1_AS_STRIDE + a_k0) * 4,
             &A[(size_t)(m0 + a_m0) * IN_DIM + k0 + a_k0], sz0);
        int sz1 = (m0 + a_m1 < M) ? 16 : 0;
        cp16(abase + (uint32_t)(a_m1 * G1_AS_STRIDE + a_k1) * 4,
             &A[(size_t)(m0 + a_m1) * IN_DIM + k0 + a_k1], sz1);
        cp16(bbase + (uint32_t)(b_kk * G1_BS_STRIDE + b_nn4) * 4,
             &W1[(size_t)(k0 + b_kk) * HID_DIM + n0 + b_nn4], 16);
        CP_COMMIT();
    };

    issue(0, 0);
    issue(1, 1);

    int b = 0;
    for (int kc = 0; kc < G1_NCHUNK; kc++) {
        if (kc + 2 < G1_NCHUNK) {
            int b2 = kc + 2;
            b2 -= (b2 >= 3) ? 3 : 0;
            b2 -= (b2 >= 3) ? 3 : 0;   // (kc+2) % 3 without div
            // recompute properly: b cycles 0,1,2; buffer for kc+2 is (b+2)%3
            int nb = b + 2; if (nb >= 3) nb -= 3;
            issue(kc + 2, nb);
            CP_WAIT(2);
        } else if (kc + 1 < G1_NCHUNK) {
            CP_WAIT(1);
        } else {
            CP_WAIT(0);
        }
        __syncthreads();

#pragma unroll
        for (int ks = 0; ks < 2; ks++) {
            const int k = ks * 8;
            uint32_t bf[4][2];
#pragma unroll
            for (int nt = 0; nt < 4; nt++) {
                int cn = warpN * 32 + nt * 8 + grp;
                bf[nt][0] = Bs[b][k + qid][cn];
                bf[nt][1] = Bs[b][k + 4 + qid][cn];
            }
#pragma unroll
            for (int mt = 0; mt < 2; mt++) {
                int rm = warpM * 32 + mt * 16 + grp;
                uint32_t a0 = As[b][rm][k + qid];
                uint32_t a1 = As[b][rm + 8][k + qid];
                uint32_t a2 = As[b][rm][k + 4 + qid];
                uint32_t a3 = As[b][rm + 8][k + 4 + qid];
#pragma unroll
                for (int nt = 0; nt < 4; nt++)
                    mma_tf32(acc[mt][nt], a0, a1, a2, a3, bf[nt][0], bf[nt][1]);
            }
        }
        __syncthreads();
        b++; if (b == 3) b = 0;
    }

    // Epilogue: bias + relu, float2 pairs
#pragma unroll
    for (int nt = 0; nt < 4; nt++) {
        int col = n0 + warpN * 32 + nt * 8 + 2 * qid;
        float bb0 = __ldg(&bias[col]);
        float bb1 = __ldg(&bias[col + 1]);
#pragma unroll
        for (int mt = 0; mt < 2; mt++) {
            int r0 = m0 + warpM * 32 + mt * 16 + grp;
            if (r0 < M) {
                float2 v = make_float2(fmaxf(acc[mt][nt][0] + bb0, 0.f),
                                       fmaxf(acc[mt][nt][1] + bb1, 0.f));
                *(float2*)&g_hidden[(size_t)r0 * HID_DIM + col] = v;
            }
            if (r0 + 8 < M) {
                float2 v = make_float2(fmaxf(acc[mt][nt][2] + bb0, 0.f),
                                       fmaxf(acc[mt][nt][3] + bb1, 0.f));
                *(float2*)&g_hidden[(size_t)(r0 + 8) * HID_DIM + col] = v;
            }
        }
    }
}

// ---------------------------------------------------------------------------
// GEMM2: h0 = hidden[M,256] @ W2[256,48] + b2  (SIMT)
// ---------------------------------------------------------------------------
__global__ __launch_bounds__(256) void gemm2_kernel(
    const float* __restrict__ W2, const float* __restrict__ b2, int M)
{
    __shared__ float Ws[64][48];
    const int tid = threadIdx.x;
    const int row = blockIdx.x * 128 + (tid >> 1);
    const int half = tid & 1;
    const bool ok = (row < M);

    float acc[24];
#pragma unroll
    for (int j = 0; j < 24; j++) acc[j] = 0.f;

    const float4* hid4 = (const float4*)g_hidden;
    for (int kc = 0; kc < 4; kc++) {
        __syncthreads();
        for (int i = tid; i < 64 * 48; i += 256) {
            int kk = i / 48, c = i - kk * 48;
            Ws[kk][c] = W2[(kc * 64 + kk) * 48 + c];
        }
        __syncthreads();
        if (ok) {
#pragma unroll
            for (int k4 = 0; k4 < 16; k4++) {
                float4 a = hid4[(size_t)row * 64 + kc * 16 + k4];
                float av[4] = {a.x, a.y, a.z, a.w};
#pragma unroll
                for (int q = 0; q < 4; q++)
#pragma unroll
                    for (int j = 0; j < 24; j++)
                        acc[j] += av[q] * Ws[k4 * 4 + q][half * 24 + j];
            }
        }
    }
    if (ok) {
#pragma unroll
        for (int j = 0; j < 24; j++)
            g_h0[(size_t)row * 48 + half * 24 + j] = acc[j] + b2[half * 24 + j];
    }
}

// ---------------------------------------------------------------------------
// Propagation (CSR, fused, atomic-free)
// ---------------------------------------------------------------------------
__global__ void hs0_kernel(int n4) {
    int i = blockIdx.x * blockDim.x + threadIdx.x;
    if (i >= n4) return;
    int row = i / 12;
    float no = g_norm_out[row];
    float4 v = ((const float4*)g_h0)[i];
    ((float4*)g_hsA)[i] = make_float4(v.x * no, v.y * no, v.z * no, v.w * no);
}

__global__ __launch_bounds__(384) void agg_kernel(
    float* __restrict__ dout, int parity, int last, int n)
{
    int t = blockIdx.x * 384 + threadIdx.x;
    int g = t / 12;
    int c = t - g * 12;
    if (g >= n) return;

    const float4* hin  = (const float4*)(parity ? g_hsB : g_hsA);
    float4*       hout = (float4*)(parity ? g_hsA : g_hsB);

    int i   = g_off[g];
    int end = g_off[g + 1];
    float4 acc = make_float4(0.f, 0.f, 0.f, 0.f);

    for (; i + 3 < end; i += 4) {
        int s0 = __ldg(&g_csr_src[i]);
        int s1 = __ldg(&g_csr_src[i + 1]);
        int s2 = __ldg(&g_csr_src[i + 2]);
        int s3 = __ldg(&g_csr_src[i + 3]);
        float4 v0 = hin[(size_t)s0 * 12 + c];
        float4 v1 = hin[(size_t)s1 * 12 + c];
        float4 v2 = hin[(size_t)s2 * 12 + c];
        float4 v3 = hin[(size_t)s3 * 12 + c];
        acc.x += v0.x + v1.x + v2.x + v3.x;
        acc.y += v0.y + v1.y + v2.y + v3.y;
        acc.z += v0.z + v1.z + v2.z + v3.z;
        acc.w += v0.w + v1.w + v2.w + v3.w;
    }
    for (; i < end; i++) {
        int s = __ldg(&g_csr_src[i]);
        float4 v = hin[(size_t)s * 12 + c];
        acc.x += v.x; acc.y += v.y; acc.z += v.z; acc.w += v.w;
    }

    float ni = g_norm_in[g];
    float4 z = ((const float4*)g_h0)[(size_t)g * 12 + c];
    float4 h = make_float4(0.9f * acc.x * ni + 0.1f * z.x,
                           0.9f * acc.y * ni + 0.1f * z.y,
                           0.9f * acc.z * ni + 0.1f * z.z,
                           0.9f * acc.w * ni + 0.1f * z.w);
    if (last) {
        ((float4*)dout)[(size_t)g * 12 + c] = h;
    } else {
        float no = g_norm_out[g];
        hout[(size_t)g * 12 + c] = make_float4(h.x * no, h.y * no, h.z * no, h.w * no);
    }
}

// ---------------------------------------------------------------------------
extern "C" void kernel_launch(void* const* d_in, const int* in_sizes, int n_in,
                              void* d_out, int out_size)
{
    const float* feats = (const float*)d_in[0];
    const int*   src   = (const int*)d_in[1];
    const int*   dst   = (const int*)d_in[2];
    const float* W1    = (const float*)d_in[3];
    const float* b1    = (const float*)d_in[4];
    const float* W2    = (const float*)d_in[5];
    const float* b2    = (const float*)d_in[6];

    const int N = in_sizes[0] / IN_DIM;
    const int E = in_sizes[1];

    // degrees + norms
    zero_deg_kernel<<<(N + 255) / 256, 256>>>(N);
    deg_kernel<<<(E + 255) / 256, 256>>>(src, dst, E);
    norm_kernel<<<(N + 255) / 256, 256>>>(N);

    // CSR build (by dst)
    const int scanBlocks = (N + 255) / 256;
    scanA_kernel<<<scanBlocks, 256>>>(N);
    scanB_kernel<<<1, 512>>>(scanBlocks);
    scanC_kernel<<<scanBlocks, 256>>>(N);
    cursor_init_kernel<<<(N + 255) / 256, 256>>>(N);
    scatter_kernel<<<(E + 255) / 256, 256>>>(src, dst, E);

    // MLP (static smem only — no attribute calls)
    dim3 g1(HID_DIM / 64, (N + 127) / 128);
    gemm1_mma_kernel<<<g1, 256>>>(feats, W1, b1, N);
    gemm2_kernel<<<(N + 127) / 128, 256>>>(W2, b2, N);

    // propagation
    const int n4 = N * 12;
    hs0_kernel<<<(n4 + 255) / 256, 256>>>(n4);
    const int aggBlocks = (N * 12 + 383) / 384;
    for (int k = 0; k < 10; k++) {
        agg_kernel<<<aggBlocks, 384>>>((float*)d_out, k & 1, k == 9 ? 1 : 0, N);
    }
    (void)n_in; (void)out_size;
}